// round 3
// baseline (speedup 1.0000x reference)
#include <cuda_runtime.h>
#include <cuda_bf16.h>

#define NN 50000
#define NE 800000

__device__ float g_deg[NN];
__device__ float g_dinv[NN];
__device__ float g_H[NN * 128];      // linear output of current layer
__device__ float g_AGG[NN * 128];    // aggregation accumulator
__device__ float g_hidden[NN * 128]; // relu(layer1) activations

// ---------------------------------------------------------------------------
// Degree / normalization
// ---------------------------------------------------------------------------
__global__ void init_deg_kernel() {
    int i = blockIdx.x * blockDim.x + threadIdx.x;
    if (i < NN) g_deg[i] = 1.0f;  // self-loop contributes 1
}

__global__ void accum_deg_kernel(const int* __restrict__ ei) {
    int e = blockIdx.x * blockDim.x + threadIdx.x;
    if (e < NE) {
        int col = ei[NE + e];  // target node
        atomicAdd(&g_deg[col], 1.0f);
    }
}

__global__ void dinv_kernel() {
    int i = blockIdx.x * blockDim.x + threadIdx.x;
    if (i < NN) g_dinv[i] = rsqrtf(g_deg[i]);  // deg >= 1 always
}

// ---------------------------------------------------------------------------
// GEMM: H = X @ W  (X: [NN,128], W: [128,128]).
// use_hidden != 0 -> X comes from g_hidden (X arg ignored).
// Wb != nullptr -> W = [Wa | Wb], each [128,64] (layers 2+3 fused).
// Epilogue: H stored, and AGG initialized with the self-loop term
// H * dinv[row]^2, so scatter only adds edge contributions.
// Block: 256 threads, 64 rows x 128 cols; thread = 8 rows x 4 cols.
// ---------------------------------------------------------------------------
__global__ __launch_bounds__(256, 2)
void gemm_kernel(const float* __restrict__ Xin,
                 const float* __restrict__ Wa,
                 const float* __restrict__ Wb,
                 int use_hidden) {
    extern __shared__ float4 smem[];
    float4* sw = smem;               // [128][32] float4 = 64 KB
    float4* sx = smem + 128 * 32;    // [64][32]  float4 = 32 KB

    const float* X = use_hidden ? g_hidden : Xin;

    const int tid = threadIdx.x;
    const int tx = tid & 31;         // cols tx*4 .. tx*4+3
    const int ty = tid >> 5;         // row group base
    const int row0 = blockIdx.x * 64;

    for (int i = tid; i < 128 * 32; i += 256) {
        int k  = i >> 5;
        int c4 = (i & 31) << 2;
        float4 v;
        if (Wb == nullptr) {
            v = *(const float4*)(Wa + k * 128 + c4);
        } else if (c4 < 64) {
            v = *(const float4*)(Wa + k * 64 + c4);
        } else {
            v = *(const float4*)(Wb + k * 64 + (c4 - 64));
        }
        sw[i] = v;
    }
    for (int i = tid; i < 64 * 32; i += 256) {
        int r = i >> 5;
        int k4 = i & 31;
        int row = row0 + r;
        float4 v = make_float4(0.f, 0.f, 0.f, 0.f);
        if (row < NN) v = *(const float4*)(X + row * 128 + k4 * 4);
        sx[i] = v;
    }
    __syncthreads();

    float acc[8][4];
#pragma unroll
    for (int r = 0; r < 8; r++)
#pragma unroll
        for (int c = 0; c < 4; c++) acc[r][c] = 0.f;

    for (int k4 = 0; k4 < 32; k4++) {
        float4 xv[8];
#pragma unroll
        for (int r = 0; r < 8; r++) xv[r] = sx[(ty + 8 * r) * 32 + k4];
#pragma unroll
        for (int kk = 0; kk < 4; kk++) {
            float4 wv = sw[(k4 * 4 + kk) * 32 + tx];
#pragma unroll
            for (int r = 0; r < 8; r++) {
                float xs = (kk == 0) ? xv[r].x : (kk == 1) ? xv[r].y
                          : (kk == 2) ? xv[r].z : xv[r].w;
                acc[r][0] += xs * wv.x;
                acc[r][1] += xs * wv.y;
                acc[r][2] += xs * wv.z;
                acc[r][3] += xs * wv.w;
            }
        }
    }

#pragma unroll
    for (int r = 0; r < 8; r++) {
        int row = row0 + ty + 8 * r;
        if (row < NN) {
            float d = g_dinv[row];
            float s = d * d;
            float4 h = make_float4(acc[r][0], acc[r][1], acc[r][2], acc[r][3]);
            *(float4*)(g_H + row * 128 + tx * 4) = h;
            float4 a = make_float4(h.x * s, h.y * s, h.z * s, h.w * s);
            *(float4*)(g_AGG + row * 128 + tx * 4) = a;
        }
    }
}

// ---------------------------------------------------------------------------
// Edge scatter: one warp per edge, lane covers 4 channels (float4).
// AGG[col] += H[row] * dinv[row]*dinv[col] via red.global.add.v4.f32.
// ---------------------------------------------------------------------------
__global__ void scatter_kernel(const int* __restrict__ ei) {
    const int lane = threadIdx.x & 31;
    int wid = (blockIdx.x * blockDim.x + threadIdx.x) >> 5;
    const int nw = (gridDim.x * blockDim.x) >> 5;
    for (int e = wid; e < NE; e += nw) {
        int row = ei[e];             // broadcast (same addr all lanes)
        int col = ei[NE + e];
        float w = g_dinv[row] * g_dinv[col];
        float4 v = *(const float4*)(g_H + row * 128 + lane * 4);
        float* dst = g_AGG + col * 128 + lane * 4;
        asm volatile("red.global.add.v4.f32 [%0], {%1, %2, %3, %4};"
                     :: "l"(dst), "f"(v.x * w), "f"(v.y * w),
                        "f"(v.z * w), "f"(v.w * w)
                     : "memory");
    }
}

// ---------------------------------------------------------------------------
// hidden = relu(AGG + b1)
// ---------------------------------------------------------------------------
__global__ void hidden_kernel(const float* __restrict__ b1) {
    int i = blockIdx.x * blockDim.x + threadIdx.x;  // over NN*32 float4
    if (i < NN * 32) {
        int c4 = (i & 31) * 4;
        float4 a = ((const float4*)g_AGG)[i];
        float4 b = *(const float4*)(b1 + c4);
        float4 h;
        h.x = fmaxf(a.x + b.x, 0.f);
        h.y = fmaxf(a.y + b.y, 0.f);
        h.z = fmaxf(a.z + b.z, 0.f);
        h.w = fmaxf(a.w + b.w, 0.f);
        ((float4*)g_hidden)[i] = h;
    }
}

// ---------------------------------------------------------------------------
// out: x1 = relu(AGG[:, :64] + b2) -> out[0 : NN*64]
//      x2 = relu(AGG[:, 64:] + b3) -> out[NN*64 : 2*NN*64]
// ---------------------------------------------------------------------------
__global__ void out_kernel(const float* __restrict__ b2,
                           const float* __restrict__ b3,
                           float* __restrict__ out) {
    int i = blockIdx.x * blockDim.x + threadIdx.x;  // over NN*32 float4
    if (i < NN * 32) {
        int c4 = (i & 31) * 4;
        int row = i >> 5;
        float4 a = ((const float4*)g_AGG)[i];
        float4 b;
        float* dst;
        if (c4 < 64) {
            b = *(const float4*)(b2 + c4);
            dst = out + row * 64 + c4;
        } else {
            b = *(const float4*)(b3 + (c4 - 64));
            dst = out + NN * 64 + row * 64 + (c4 - 64);
        }
        float4 r;
        r.x = fmaxf(a.x + b.x, 0.f);
        r.y = fmaxf(a.y + b.y, 0.f);
        r.z = fmaxf(a.z + b.z, 0.f);
        r.w = fmaxf(a.w + b.w, 0.f);
        *(float4*)dst = r;
    }
}

// ---------------------------------------------------------------------------
extern "C" void kernel_launch(void* const* d_in, const int* in_sizes, int n_in,
                              void* d_out, int out_size) {
    const float* x  = (const float*)d_in[0];
    const int*   ei = (const int*)d_in[1];   // int32: JAX default (no x64)
    const float* W1 = (const float*)d_in[2];
    const float* b1 = (const float*)d_in[3];
    const float* W2 = (const float*)d_in[4];
    const float* b2 = (const float*)d_in[5];
    const float* W3 = (const float*)d_in[6];
    const float* b3 = (const float*)d_in[7];
    float* out = (float*)d_out;

    const int smem = 96 * 1024;
    cudaFuncSetAttribute(gemm_kernel,
                         cudaFuncAttributeMaxDynamicSharedMemorySize, smem);

    const int gemm_blocks = (NN + 63) / 64;  // 782
    const int ew_blocks = 1184;              // scatter: ~8 blocks/SM

    // Degree + dinv
    init_deg_kernel<<<(NN + 255) / 256, 256>>>();
    accum_deg_kernel<<<(NE + 255) / 256, 256>>>(ei);
    dinv_kernel<<<(NN + 255) / 256, 256>>>();

    // Layer 1
    gemm_kernel<<<gemm_blocks, 256, smem>>>(x, W1, nullptr, 0);
    scatter_kernel<<<ew_blocks, 256>>>(ei);
    hidden_kernel<<<(NN * 32 + 255) / 256, 256>>>(b1);

    // Layers 2+3 fused
    gemm_kernel<<<gemm_blocks, 256, smem>>>(nullptr, W2, W3, 1);
    scatter_kernel<<<ew_blocks, 256>>>(ei);
    out_kernel<<<(NN * 32 + 255) / 256, 256>>>(b2, b3, out);
}

// round 4
// speedup vs baseline: 1.0173x; 1.0173x over previous
#include <cuda_runtime.h>
#include <cuda_bf16.h>

#define NN 50000
#define NE 800000

__device__ int   g_cnt[NN];          // in-degree histogram (excl. self-loop)
__device__ int   g_off[NN + 1];      // CSR offsets
__device__ int   g_cur[NN];          // fill cursors
__device__ int   g_csr_row[NE];      // source node per CSR slot
__device__ float g_csr_w[NE];        // dinv[source] per CSR slot
__device__ float g_dinv[NN];
__device__ float g_H[NN * 128];      // linear output of current layer
__device__ float g_hidden[NN * 128]; // relu(layer1) activations

// ---------------------------------------------------------------------------
// CSR build: histogram -> scan (+dinv) -> fill
// ---------------------------------------------------------------------------
__global__ void zero_cnt_kernel() {
    int i = blockIdx.x * blockDim.x + threadIdx.x;
    if (i < NN) g_cnt[i] = 0;
}

__global__ void hist_kernel(const int* __restrict__ ei) {
    int e = blockIdx.x * blockDim.x + threadIdx.x;
    if (e < NE) atomicAdd(&g_cnt[ei[NE + e]], 1);
}

// Single block, 1024 threads: exclusive scan of g_cnt, plus cursor + dinv.
__global__ void scan_kernel() {
    __shared__ int ssum[1024];
    const int t = threadIdx.x;
    const int CH = (NN + 1023) / 1024;  // 49
    int lo = t * CH;
    int hi = min(lo + CH, NN);
    int sum = 0;
    for (int k = lo; k < hi; k++) sum += g_cnt[k];
    ssum[t] = sum;
    __syncthreads();
    for (int d = 1; d < 1024; d <<= 1) {
        int v = ssum[t];
        int add = (t >= d) ? ssum[t - d] : 0;
        __syncthreads();
        ssum[t] = v + add;
        __syncthreads();
    }
    int run = (t > 0) ? ssum[t - 1] : 0;
    for (int k = lo; k < hi; k++) {
        g_off[k] = run;
        g_cur[k] = run;
        g_dinv[k] = rsqrtf((float)(1 + g_cnt[k]));  // deg includes self-loop
        run += g_cnt[k];
    }
    if (t == 1023) g_off[NN] = run;
}

__global__ void fill_kernel(const int* __restrict__ ei) {
    int e = blockIdx.x * blockDim.x + threadIdx.x;
    if (e < NE) {
        int row = ei[e];
        int col = ei[NE + e];
        int pos = atomicAdd(&g_cur[col], 1);
        g_csr_row[pos] = row;
        g_csr_w[pos]   = g_dinv[row];
    }
}

// ---------------------------------------------------------------------------
// GEMM: g_H = X @ W  (X: [NN,128], W: [128,128]).
// use_hidden != 0 -> X comes from g_hidden.
// Wb != nullptr -> W = [Wa | Wb], each [128,64] (layers 2+3 fused).
// Block: 256 threads, 64 rows x 128 cols; thread = 8 rows x 4 cols.
// ---------------------------------------------------------------------------
__global__ __launch_bounds__(256, 2)
void gemm_kernel(const float* __restrict__ Xin,
                 const float* __restrict__ Wa,
                 const float* __restrict__ Wb,
                 int use_hidden) {
    extern __shared__ float4 smem[];
    float4* sw = smem;               // [128][32] float4 = 64 KB
    float4* sx = smem + 128 * 32;    // [64][32]  float4 = 32 KB

    const float* X = use_hidden ? g_hidden : Xin;

    const int tid = threadIdx.x;
    const int tx = tid & 31;         // cols tx*4 .. tx*4+3
    const int ty = tid >> 5;         // row group base
    const int row0 = blockIdx.x * 64;

    for (int i = tid; i < 128 * 32; i += 256) {
        int k  = i >> 5;
        int c4 = (i & 31) << 2;
        float4 v;
        if (Wb == nullptr) {
            v = *(const float4*)(Wa + k * 128 + c4);
        } else if (c4 < 64) {
            v = *(const float4*)(Wa + k * 64 + c4);
        } else {
            v = *(const float4*)(Wb + k * 64 + (c4 - 64));
        }
        sw[i] = v;
    }
    for (int i = tid; i < 64 * 32; i += 256) {
        int r = i >> 5;
        int k4 = i & 31;
        int row = row0 + r;
        float4 v = make_float4(0.f, 0.f, 0.f, 0.f);
        if (row < NN) v = *(const float4*)(X + row * 128 + k4 * 4);
        sx[i] = v;
    }
    __syncthreads();

    float acc[8][4];
#pragma unroll
    for (int r = 0; r < 8; r++)
#pragma unroll
        for (int c = 0; c < 4; c++) acc[r][c] = 0.f;

    for (int k4 = 0; k4 < 32; k4++) {
        float4 xv[8];
#pragma unroll
        for (int r = 0; r < 8; r++) xv[r] = sx[(ty + 8 * r) * 32 + k4];
#pragma unroll
        for (int kk = 0; kk < 4; kk++) {
            float4 wv = sw[(k4 * 4 + kk) * 32 + tx];
#pragma unroll
            for (int r = 0; r < 8; r++) {
                float xs = (kk == 0) ? xv[r].x : (kk == 1) ? xv[r].y
                          : (kk == 2) ? xv[r].z : xv[r].w;
                acc[r][0] += xs * wv.x;
                acc[r][1] += xs * wv.y;
                acc[r][2] += xs * wv.z;
                acc[r][3] += xs * wv.w;
            }
        }
    }

#pragma unroll
    for (int r = 0; r < 8; r++) {
        int row = row0 + ty + 8 * r;
        if (row < NN) {
            float4 h = make_float4(acc[r][0], acc[r][1], acc[r][2], acc[r][3]);
            *(float4*)(g_H + row * 128 + tx * 4) = h;
        }
    }
}

// ---------------------------------------------------------------------------
// CSR aggregation, fused epilogue. One warp per target node.
//   res = dinv[i] * ( dinv[i]*H[i] + sum_e dinv[row_e]*H[row_e] )
// layer==1: g_hidden[i] = relu(res + b1)
// layer==2: out[i, :64] = relu(res_lo + b2); out[NN*64 + i*64 + c] = relu(res_hi + b3)
// ---------------------------------------------------------------------------
__global__ void agg_kernel(int layer,
                           const float* __restrict__ bA,
                           const float* __restrict__ bB,
                           float* __restrict__ out) {
    int warp = (blockIdx.x * blockDim.x + threadIdx.x) >> 5;
    if (warp >= NN) return;
    const int lane = threadIdx.x & 31;
    const int i = warp;
    const int s = g_off[i];
    const int e = g_off[i + 1];
    const float di = g_dinv[i];

    // self-loop term (weight dinv[i]; outer dinv[i] applied at the end)
    float4 hv = *(const float4*)(g_H + i * 128 + lane * 4);
    float4 acc = make_float4(hv.x * di, hv.y * di, hv.z * di, hv.w * di);

    for (int base = s; base < e; base += 32) {
        int j = base + lane;
        int r = 0;
        float w = 0.f;
        if (j < e) { r = g_csr_row[j]; w = g_csr_w[j]; }
        int cnt = min(32, e - base);
        for (int k = 0; k < cnt; k++) {
            int   rr = __shfl_sync(0xffffffffu, r, k);
            float ww = __shfl_sync(0xffffffffu, w, k);
            float4 v = *(const float4*)(g_H + rr * 128 + lane * 4);
            acc.x += ww * v.x;
            acc.y += ww * v.y;
            acc.z += ww * v.z;
            acc.w += ww * v.w;
        }
    }
    acc.x *= di; acc.y *= di; acc.z *= di; acc.w *= di;

    const int c4 = lane * 4;
    if (layer == 1) {
        float4 b = *(const float4*)(bA + c4);
        float4 h;
        h.x = fmaxf(acc.x + b.x, 0.f);
        h.y = fmaxf(acc.y + b.y, 0.f);
        h.z = fmaxf(acc.z + b.z, 0.f);
        h.w = fmaxf(acc.w + b.w, 0.f);
        *(float4*)(g_hidden + i * 128 + c4) = h;
    } else {
        float4 b;
        float* dst;
        if (c4 < 64) {
            b = *(const float4*)(bA + c4);
            dst = out + i * 64 + c4;
        } else {
            b = *(const float4*)(bB + (c4 - 64));
            dst = out + NN * 64 + i * 64 + (c4 - 64);
        }
        float4 r;
        r.x = fmaxf(acc.x + b.x, 0.f);
        r.y = fmaxf(acc.y + b.y, 0.f);
        r.z = fmaxf(acc.z + b.z, 0.f);
        r.w = fmaxf(acc.w + b.w, 0.f);
        *(float4*)dst = r;
    }
}

// ---------------------------------------------------------------------------
extern "C" void kernel_launch(void* const* d_in, const int* in_sizes, int n_in,
                              void* d_out, int out_size) {
    const float* x  = (const float*)d_in[0];
    const int*   ei = (const int*)d_in[1];   // int32 (JAX default, no x64)
    const float* W1 = (const float*)d_in[2];
    const float* b1 = (const float*)d_in[3];
    const float* W2 = (const float*)d_in[4];
    const float* b2 = (const float*)d_in[5];
    const float* W3 = (const float*)d_in[6];
    const float* b3 = (const float*)d_in[7];
    float* out = (float*)d_out;

    const int smem = 96 * 1024;
    cudaFuncSetAttribute(gemm_kernel,
                         cudaFuncAttributeMaxDynamicSharedMemorySize, smem);

    const int gemm_blocks = (NN + 63) / 64;      // 782
    const int agg_blocks  = (NN + 7) / 8;        // 8 warps/block, 1 node/warp

    // CSR build (shared by both layers) + dinv
    zero_cnt_kernel<<<(NN + 255) / 256, 256>>>();
    hist_kernel<<<(NE + 255) / 256, 256>>>(ei);
    scan_kernel<<<1, 1024>>>();
    fill_kernel<<<(NE + 255) / 256, 256>>>(ei);

    // Layer 1: H = x@W1 ; agg -> hidden (bias+relu fused)
    gemm_kernel<<<gemm_blocks, 256, smem>>>(x, W1, nullptr, 0);
    agg_kernel<<<agg_blocks, 256>>>(1, b1, nullptr, nullptr);

    // Layers 2+3 fused: H = hidden@[W2|W3] ; agg -> out (bias+relu+split fused)
    gemm_kernel<<<gemm_blocks, 256, smem>>>(nullptr, W2, W3, 1);
    agg_kernel<<<agg_blocks, 256>>>(2, b2, b3, out);
}